// round 1
// baseline (speedup 1.0000x reference)
#include <cuda_runtime.h>
#include <cuda_bf16.h>
#include <cstdint>

#define GRID_DIM 201
#define OFFSET 100

__global__ void zero_out_kernel(float* out) {
    out[0] = 0.0f;
}

__global__ void __launch_bounds__(256)
wmse_kernel(const float* __restrict__ pred,
            const float* __restrict__ lab,
            const float* __restrict__ wg,
            float* __restrict__ out,
            int nvec,           // number of float4 chunks (each = 2 samples)
            float inv_count)    // 1 / (B*2)
{
    const float4* __restrict__ p4 = reinterpret_cast<const float4*>(pred);
    const float4* __restrict__ l4 = reinterpret_cast<const float4*>(lab);

    float acc = 0.0f;
    int stride = gridDim.x * blockDim.x;
    for (int i = blockIdx.x * blockDim.x + threadIdx.x; i < nvec; i += stride) {
        float4 p = p4[i];
        float4 l = l4[i];

        // ---- sample 0: (p.x = lat-norm, p.y = lon-norm) ----
        {
            float e0 = fabsf(p.x - l.x);
            float e1 = fabsf(p.y - l.y);
            float lat = p.x * 180.0f - 90.0f;
            float lon = p.y * 360.0f - 180.0f;
            int xi = (int)floorf(lat / 0.9f) + OFFSET;
            int yi = (int)floorf(lon / 1.8f) + OFFSET;
            xi = min(max(xi, 0), GRID_DIM - 1);
            yi = min(max(yi, 0), GRID_DIM - 1);
            float w = __ldg(&wg[xi * GRID_DIM + yi]);
            float f = 1.1f - 0.1f * w;   // 1 + alpha - alpha*w
            acc += (e0 + e1) * f;
        }
        // ---- sample 1: (p.z, p.w) ----
        {
            float e0 = fabsf(p.z - l.z);
            float e1 = fabsf(p.w - l.w);
            float lat = p.z * 180.0f - 90.0f;
            float lon = p.w * 360.0f - 180.0f;
            int xi = (int)floorf(lat / 0.9f) + OFFSET;
            int yi = (int)floorf(lon / 1.8f) + OFFSET;
            xi = min(max(xi, 0), GRID_DIM - 1);
            yi = min(max(yi, 0), GRID_DIM - 1);
            float w = __ldg(&wg[xi * GRID_DIM + yi]);
            float f = 1.1f - 0.1f * w;
            acc += (e0 + e1) * f;
        }
    }

    // warp reduction
    #pragma unroll
    for (int off = 16; off > 0; off >>= 1)
        acc += __shfl_xor_sync(0xFFFFFFFFu, acc, off);

    __shared__ float warp_part[8];
    int lane = threadIdx.x & 31;
    int wid  = threadIdx.x >> 5;
    if (lane == 0) warp_part[wid] = acc;
    __syncthreads();

    if (wid == 0) {
        float v = (lane < (blockDim.x >> 5)) ? warp_part[lane] : 0.0f;
        #pragma unroll
        for (int off = 4; off > 0; off >>= 1)
            v += __shfl_xor_sync(0xFFFFFFFFu, v, off);
        if (lane == 0)
            atomicAdd(out, v * inv_count);
    }
}

extern "C" void kernel_launch(void* const* d_in, const int* in_sizes, int n_in,
                              void* d_out, int out_size) {
    const float* pred = (const float*)d_in[0];
    const float* lab  = (const float*)d_in[1];
    const float* wg   = (const float*)d_in[2];
    float* out = (float*)d_out;

    int total = in_sizes[0];          // B*2 floats
    int nvec  = total / 4;            // float4 chunks
    float inv_count = 1.0f / (float)total;

    zero_out_kernel<<<1, 1>>>(out);

    int threads = 256;
    int blocks  = 148 * 8;            // 8 CTAs/SM, full-chip wave
    wmse_kernel<<<blocks, threads>>>(pred, lab, wg, out, nvec, inv_count);
}